// round 2
// baseline (speedup 1.0000x reference)
#include <cuda_runtime.h>
#include <cstdint>

#define D_MODEL 1024
#define D_FF    4096
#define N_EXP   8
#define TOPK    2
#define MAX_T   4096
#define MAX_ROWS (MAX_T * TOPK)

// ---------------- scratch (device globals; no allocation allowed) ----------------
__device__ float g_gw[MAX_T * TOPK];     // softmax weights per (t,k)
__device__ int   g_geid[MAX_T * TOPK];   // expert id per (t,k)
__device__ int   g_rowof[MAX_T * TOPK];  // (t,k) -> compact row
__device__ int   g_tok[MAX_ROWS];        // compact row -> token
__device__ int   g_cnt[N_EXP];
__device__ int   g_off[N_EXP];
__device__ int   g_pos[N_EXP];
__device__ float g_h[(size_t)MAX_ROWS * D_FF];     // 128 MB hidden acts
__device__ float g_y[(size_t)MAX_ROWS * D_MODEL];  // 32 MB expert outputs

// ---------------- kernels ----------------
__global__ void zero_kernel() {
    int i = threadIdx.x;
    if (i < N_EXP) { g_cnt[i] = 0; g_pos[i] = 0; }
}

// one warp per token: 8 gate logits, top-2, softmax, count
__global__ void gate_kernel(const float* __restrict__ x,
                            const float* __restrict__ Wg, int T) {
    int gwarp = (blockIdx.x * blockDim.x + threadIdx.x) >> 5;
    int lane  = threadIdx.x & 31;
    if (gwarp >= T) return;
    const float* xr = x + (size_t)gwarp * D_MODEL;
    float acc[N_EXP];
#pragma unroll
    for (int e = 0; e < N_EXP; e++) acc[e] = 0.f;
    for (int d = lane; d < D_MODEL; d += 32) {
        float xv = xr[d];
        const float* wr = Wg + d * N_EXP;
#pragma unroll
        for (int e = 0; e < N_EXP; e++) acc[e] += xv * wr[e];
    }
#pragma unroll
    for (int e = 0; e < N_EXP; e++)
#pragma unroll
        for (int o = 16; o > 0; o >>= 1)
            acc[e] += __shfl_xor_sync(0xFFFFFFFFu, acc[e], o);
    if (lane == 0) {
        int e0 = 0;
#pragma unroll
        for (int e = 1; e < N_EXP; e++) if (acc[e] > acc[e0]) e0 = e;
        int e1 = -1;
#pragma unroll
        for (int e = 0; e < N_EXP; e++) {
            if (e == e0) continue;
            if (e1 < 0 || acc[e] > acc[e1]) e1 = e;
        }
        float l0 = acc[e0], l1 = acc[e1];
        float z1 = __expf(l1 - l0);           // l0 is max
        float s  = 1.f + z1;
        g_gw[2 * gwarp]     = 1.f / s;
        g_gw[2 * gwarp + 1] = z1  / s;
        g_geid[2 * gwarp]     = e0;
        g_geid[2 * gwarp + 1] = e1;
        atomicAdd(&g_cnt[e0], 1);
        atomicAdd(&g_cnt[e1], 1);
    }
}

// single block: exclusive scan of counts, then assign compact rows
__global__ void route_kernel(int T) {
    if (threadIdx.x == 0) {
        int s = 0;
#pragma unroll
        for (int e = 0; e < N_EXP; e++) { g_off[e] = s; s += g_cnt[e]; }
    }
    __syncthreads();
    int A = T * TOPK;
    for (int a = threadIdx.x; a < A; a += blockDim.x) {
        int e = g_geid[a];
        int p = atomicAdd(&g_pos[e], 1);
        int r = g_off[e] + p;
        g_rowof[a] = r;
        g_tok[r]   = a >> 1;
    }
}

// grouped GEMM: C[rows_e, N] = A[rows_e, K] * W[e] (+bias) (opt relu)
// BM=BN=64, BK=16, 256 threads, 4x4 microtile
// NOTE: As row stride is 68 floats (= 272 B = 17*16) so that float4 reads
// &As[k][ty*4] stay 16B-aligned for every k. 68 mod 32 = 4 -> bank skew kept.
template <bool GATHER, bool RELU>
__global__ void __launch_bounds__(256)
gemm_kernel(const float* __restrict__ Asrc,
            const float* __restrict__ Wbase,
            const float* __restrict__ bias,
            float* __restrict__ Cdst,
            int K, int N) {
    const int e   = blockIdx.z;
    const int cnt = g_cnt[e];
    const int m0  = blockIdx.y * 64;
    if (m0 >= cnt) return;
    const int off  = g_off[e];
    const int n0   = blockIdx.x * 64;
    const int rows = min(64, cnt - m0);
    const float* __restrict__ B = Wbase + (size_t)e * K * N;

    __shared__ __align__(16) float As[16][68];
    __shared__ __align__(16) float Bs[16][64];

    const int tid = threadIdx.x;
    const int tx  = tid & 15;      // 0..15
    const int ty  = tid >> 4;      // 0..15

    float acc[4][4];
#pragma unroll
    for (int i = 0; i < 4; i++)
#pragma unroll
        for (int j = 0; j < 4; j++) acc[i][j] = 0.f;

    // per-thread A row pointers (load rows ty+16*i, clamped to valid range)
    const float* arow[4];
#pragma unroll
    for (int i = 0; i < 4; i++) {
        int m  = ty + 16 * i;
        int mr = min(m, rows - 1);
        int gr = off + m0 + mr;
        arow[i] = GATHER ? (Asrc + (size_t)g_tok[gr] * K)
                         : (Asrc + (size_t)gr * K);
    }

    for (int k0 = 0; k0 < K; k0 += 16) {
#pragma unroll
        for (int i = 0; i < 4; i++)
            As[tx][ty + 16 * i] = arow[i][k0 + tx];
        float4 bv = *reinterpret_cast<const float4*>(
            B + (size_t)(k0 + ty) * N + n0 + tx * 4);
        *reinterpret_cast<float4*>(&Bs[ty][tx * 4]) = bv;
        __syncthreads();
#pragma unroll
        for (int k = 0; k < 16; k++) {
            float4 a4 = *reinterpret_cast<const float4*>(&As[k][ty * 4]);
            float4 b4 = *reinterpret_cast<const float4*>(&Bs[k][tx * 4]);
            float a[4] = {a4.x, a4.y, a4.z, a4.w};
            float b[4] = {b4.x, b4.y, b4.z, b4.w};
#pragma unroll
            for (int i = 0; i < 4; i++)
#pragma unroll
                for (int j = 0; j < 4; j++) acc[i][j] += a[i] * b[j];
        }
        __syncthreads();
    }

    const float* brow = bias + e * N + n0 + tx * 4;
    float bb[4] = {brow[0], brow[1], brow[2], brow[3]};
#pragma unroll
    for (int i = 0; i < 4; i++) {
        int m = ty * 4 + i;
        if (m < rows) {
            size_t gr = (size_t)(off + m0 + m);
            float4 v;
            float* vp = &v.x;
#pragma unroll
            for (int j = 0; j < 4; j++) {
                float c = acc[i][j] + bb[j];
                if (RELU) c = fmaxf(c, 0.f);
                vp[j] = c;
            }
            *reinterpret_cast<float4*>(Cdst + gr * N + n0 + tx * 4) = v;
        }
    }
}

// out[t] = w0*y[row0] + w1*y[row1]
__global__ void combine_kernel(float* __restrict__ out) {
    int t = blockIdx.x;
    float w0 = g_gw[2 * t], w1 = g_gw[2 * t + 1];
    const float4* y0 = reinterpret_cast<const float4*>(g_y + (size_t)g_rowof[2 * t]     * D_MODEL);
    const float4* y1 = reinterpret_cast<const float4*>(g_y + (size_t)g_rowof[2 * t + 1] * D_MODEL);
    float4* o = reinterpret_cast<float4*>(out + (size_t)t * D_MODEL);
    int i = threadIdx.x;                  // 256 threads, 256 float4 = 1024 floats
    float4 a = y0[i], b = y1[i];
    float4 r;
    r.x = w0 * a.x + w1 * b.x;
    r.y = w0 * a.y + w1 * b.y;
    r.z = w0 * a.z + w1 * b.z;
    r.w = w0 * a.w + w1 * b.w;
    o[i] = r;
}

// ---------------- launch ----------------
extern "C" void kernel_launch(void* const* d_in, const int* in_sizes, int n_in,
                              void* d_out, int out_size) {
    const float* x  = (const float*)d_in[0];   // (2,2048,1024)
    const float* Wg = (const float*)d_in[1];   // (1024,8)
    const float* W1 = (const float*)d_in[2];   // (8,1024,4096)
    const float* b1 = (const float*)d_in[3];   // (8,4096)
    const float* W2 = (const float*)d_in[4];   // (8,4096,1024)
    const float* b2 = (const float*)d_in[5];   // (8,1024)
    float* out = (float*)d_out;

    const int T = in_sizes[0] / D_MODEL;       // 4096

    float* hbuf; cudaGetSymbolAddress((void**)&hbuf, g_h);
    float* ybuf; cudaGetSymbolAddress((void**)&ybuf, g_y);

    zero_kernel<<<1, 32>>>();
    gate_kernel<<<(T * 32 + 255) / 256, 256>>>(x, Wg, T);
    route_kernel<<<1, 256>>>(T);
    // GEMM1: [rows,1024] x [1024,4096], gather + relu + b1
    gemm_kernel<true, true><<<dim3(D_FF / 64, MAX_T / 64, N_EXP), 256>>>(
        x, W1, b1, hbuf, D_MODEL, D_FF);
    // GEMM2: [rows,4096] x [4096,1024], + b2
    gemm_kernel<false, false><<<dim3(D_MODEL / 64, MAX_T / 64, N_EXP), 256>>>(
        hbuf, W2, b2, ybuf, D_FF, D_MODEL);
    combine_kernel<<<T, 256>>>(out);
}

// round 5
// speedup vs baseline: 2.4708x; 2.4708x over previous
#include <cuda_runtime.h>
#include <cuda_bf16.h>
#include <cstdint>

#define D_MODEL 1024
#define D_FF    4096
#define N_EXP   8
#define TOPK    2
#define MAX_T   4096
#define MAX_ROWS (MAX_T * TOPK)

// ---------------- scratch (device globals; no allocation allowed) ----------------
__device__ float g_gw[MAX_T * TOPK];
__device__ int   g_geid[MAX_T * TOPK];
__device__ int   g_rowof[MAX_T * TOPK];
__device__ int   g_tok[MAX_ROWS];
__device__ int   g_cnt[N_EXP];
__device__ int   g_off[N_EXP];
__device__ int   g_pos[N_EXP];

__device__ __nv_bfloat16 g_xh[(size_t)MAX_T * D_MODEL];
__device__ __nv_bfloat16 g_xl[(size_t)MAX_T * D_MODEL];
__device__ __nv_bfloat16 g_w1h[(size_t)N_EXP * D_MODEL * D_FF];   // [e][d][f] row-major
__device__ __nv_bfloat16 g_w1l[(size_t)N_EXP * D_MODEL * D_FF];
__device__ __nv_bfloat16 g_w2h[(size_t)N_EXP * D_FF * D_MODEL];   // [e][f][d]
__device__ __nv_bfloat16 g_w2l[(size_t)N_EXP * D_FF * D_MODEL];
__device__ __nv_bfloat16 g_hh[(size_t)MAX_ROWS * D_FF];
__device__ __nv_bfloat16 g_hl[(size_t)MAX_ROWS * D_FF];
__device__ float g_y[(size_t)MAX_ROWS * D_MODEL];

// ---------------- PTX helpers ----------------
__device__ __forceinline__ uint32_t smem_u32(const void* p) {
    uint32_t a;
    asm("{ .reg .u64 t; cvta.to.shared.u64 t, %1; cvt.u32.u64 %0, t; }" : "=r"(a) : "l"(p));
    return a;
}
#define CP_ASYNC16(dst, src) \
    asm volatile("cp.async.cg.shared.global [%0], [%1], 16;" :: "r"(dst), "l"(src))
#define CP_COMMIT() asm volatile("cp.async.commit_group;" ::: "memory")
#define CP_WAIT1()  asm volatile("cp.async.wait_group 1;" ::: "memory")
#define CP_WAIT0()  asm volatile("cp.async.wait_group 0;" ::: "memory")

__device__ __forceinline__ void ldsm_x4(uint32_t a, uint32_t& r0, uint32_t& r1, uint32_t& r2, uint32_t& r3) {
    asm volatile("ldmatrix.sync.aligned.m8n8.x4.shared.b16 {%0,%1,%2,%3}, [%4];"
                 : "=r"(r0), "=r"(r1), "=r"(r2), "=r"(r3) : "r"(a));
}
__device__ __forceinline__ void ldsm_x4_t(uint32_t a, uint32_t& r0, uint32_t& r1, uint32_t& r2, uint32_t& r3) {
    asm volatile("ldmatrix.sync.aligned.m8n8.x4.trans.shared.b16 {%0,%1,%2,%3}, [%4];"
                 : "=r"(r0), "=r"(r1), "=r"(r2), "=r"(r3) : "r"(a));
}
__device__ __forceinline__ void mma_bf16(float& d0, float& d1, float& d2, float& d3,
                                         uint32_t a0, uint32_t a1, uint32_t a2, uint32_t a3,
                                         uint32_t b0, uint32_t b1) {
    asm volatile("mma.sync.aligned.m16n8k16.row.col.f32.bf16.bf16.f32 "
                 "{%0,%1,%2,%3},{%4,%5,%6,%7},{%8,%9},{%0,%1,%2,%3};"
                 : "+f"(d0), "+f"(d1), "+f"(d2), "+f"(d3)
                 : "r"(a0), "r"(a1), "r"(a2), "r"(a3), "r"(b0), "r"(b1));
}

// ---------------- small kernels ----------------
__global__ void zero_kernel() {
    int i = threadIdx.x;
    if (i < N_EXP) { g_cnt[i] = 0; g_pos[i] = 0; }
}

__global__ void gate_kernel(const float* __restrict__ x,
                            const float* __restrict__ Wg, int T) {
    int gwarp = (blockIdx.x * blockDim.x + threadIdx.x) >> 5;
    int lane  = threadIdx.x & 31;
    if (gwarp >= T) return;
    const float* xr = x + (size_t)gwarp * D_MODEL;
    float acc[N_EXP];
#pragma unroll
    for (int e = 0; e < N_EXP; e++) acc[e] = 0.f;
    for (int d = lane; d < D_MODEL; d += 32) {
        float xv = xr[d];
        const float* wr = Wg + d * N_EXP;
#pragma unroll
        for (int e = 0; e < N_EXP; e++) acc[e] += xv * wr[e];
    }
#pragma unroll
    for (int e = 0; e < N_EXP; e++)
#pragma unroll
        for (int o = 16; o > 0; o >>= 1)
            acc[e] += __shfl_xor_sync(0xFFFFFFFFu, acc[e], o);
    if (lane == 0) {
        int e0 = 0;
#pragma unroll
        for (int e = 1; e < N_EXP; e++) if (acc[e] > acc[e0]) e0 = e;
        int e1 = -1;
#pragma unroll
        for (int e = 0; e < N_EXP; e++) {
            if (e == e0) continue;
            if (e1 < 0 || acc[e] > acc[e1]) e1 = e;
        }
        float l0 = acc[e0], l1 = acc[e1];
        float z1 = __expf(l1 - l0);
        float s  = 1.f + z1;
        g_gw[2 * gwarp]     = 1.f / s;
        g_gw[2 * gwarp + 1] = z1  / s;
        g_geid[2 * gwarp]     = e0;
        g_geid[2 * gwarp + 1] = e1;
        atomicAdd(&g_cnt[e0], 1);
        atomicAdd(&g_cnt[e1], 1);
    }
}

__global__ void route_kernel(int T) {
    if (threadIdx.x == 0) {
        int s = 0;
#pragma unroll
        for (int e = 0; e < N_EXP; e++) { g_off[e] = s; s += g_cnt[e]; }
    }
    __syncthreads();
    int A = T * TOPK;
    for (int a = threadIdx.x; a < A; a += blockDim.x) {
        int e = g_geid[a];
        int p = atomicAdd(&g_pos[e], 1);
        int r = g_off[e] + p;
        g_rowof[a] = r;
        g_tok[r]   = a >> 1;
    }
}

// fp32 -> bf16 hi/lo split (coalesced, x4)
__global__ void split_kernel(const float* __restrict__ in,
                             __nv_bfloat16* __restrict__ oh,
                             __nv_bfloat16* __restrict__ ol, size_t n) {
    size_t i = ((size_t)blockIdx.x * blockDim.x + threadIdx.x) * 4;
    if (i >= n) return;
    float4 v = *reinterpret_cast<const float4*>(in + i);
    float f[4] = {v.x, v.y, v.z, v.w};
    __nv_bfloat16 h[4], l[4];
#pragma unroll
    for (int j = 0; j < 4; j++) {
        h[j] = __float2bfloat16_rn(f[j]);
        l[j] = __float2bfloat16_rn(f[j] - __bfloat162float(h[j]));
    }
    __nv_bfloat162 ph0 = {h[0], h[1]}, ph1 = {h[2], h[3]};
    __nv_bfloat162 pl0 = {l[0], l[1]}, pl1 = {l[2], l[3]};
    *reinterpret_cast<__nv_bfloat162*>(oh + i)     = ph0;
    *reinterpret_cast<__nv_bfloat162*>(oh + i + 2) = ph1;
    *reinterpret_cast<__nv_bfloat162*>(ol + i)     = pl0;
    *reinterpret_cast<__nv_bfloat162*>(ol + i + 2) = pl1;
}

// ---------------- HMMA grouped GEMM ----------------
// BM=128, BN=128, BK=32. 256 threads = 8 warps (2 M x 4 N), warp tile 64x32.
// A smem: [128 rows][32 halves] pitch 80 B; B smem: [32 k-rows][128 halves] pitch 272 B.
#define A_PITCH   80
#define B_PITCH   272
#define A_BYTES   (128 * A_PITCH)          // 10240
#define B_BYTES   (32 * B_PITCH)           // 8704
#define OFF_AH    0
#define OFF_AL    A_BYTES
#define OFF_BH    (2 * A_BYTES)
#define OFF_BL    (2 * A_BYTES + B_BYTES)
#define STAGE     (2 * A_BYTES + 2 * B_BYTES)   // 37888
#define SMEM_SZ   (2 * STAGE)                   // 75776

template <bool GATHER, bool RELU, bool OUT_SPLIT>
__global__ void __launch_bounds__(256, 1)
mma_gemm(const __nv_bfloat16* __restrict__ Ah_g, const __nv_bfloat16* __restrict__ Al_g,
         const __nv_bfloat16* __restrict__ Bh_g, const __nv_bfloat16* __restrict__ Bl_g,
         const float* __restrict__ bias,
         float* __restrict__ Cf,
         __nv_bfloat16* __restrict__ Ch, __nv_bfloat16* __restrict__ Cl,
         int K, int N) {
    const int e   = blockIdx.z;
    const int cnt = g_cnt[e];
    const int m0  = blockIdx.y * 128;
    if (m0 >= cnt) return;
    const int off  = g_off[e];
    const int n0   = blockIdx.x * 128;
    const int rows = min(128, cnt - m0);

    extern __shared__ uint8_t smem[];
    const uint32_t sm = smem_u32(smem);

    const int tid  = threadIdx.x;
    const int wid  = tid >> 5;
    const int lane = tid & 31;
    const int wm   = (wid >> 2) * 64;   // warp M offset
    const int wn   = (wid & 3) * 32;    // warp N offset

    // ---- A source pointers: 2 rows per thread (row, row+64), 16B chunk acv ----
    const int ar   = tid >> 2;          // 0..63
    const int acv  = tid & 3;           // 16B chunk within 64B row
    const char *pAh[2], *pAl[2];
#pragma unroll
    for (int i = 0; i < 2; i++) {
        int r  = ar + 64 * i;
        int mr = min(r, rows - 1);
        int gr = off + m0 + mr;
        size_t srow = GATHER ? (size_t)g_tok[gr] : (size_t)gr;
        pAh[i] = (const char*)(Ah_g + srow * K) + acv * 16;
        pAl[i] = (const char*)(Al_g + srow * K) + acv * 16;
    }
    // ---- B: 2 chunks per thread covering 32 rows x 16 chunks (512 chunks) ----
    const size_t ebase = (size_t)e * K * N;
    const char* pBh_base = (const char*)(Bh_g + ebase + n0);
    const char* pBl_base = (const char*)(Bl_g + ebase + n0);
    const size_t bstride = (size_t)N * 2;   // bytes per k row
    int brow[2], bcol[2];
#pragma unroll
    for (int t = 0; t < 2; t++) {
        int idx = tid + 256 * t;
        brow[t] = idx >> 4;     // 0..31
        bcol[t] = idx & 15;     // 0..15 (16B chunks)
    }

    const int nch = K >> 5;

    auto issue = [&](int c) {
        const uint32_t st = sm + (c & 1) * STAGE;
        const size_t ka = (size_t)c * 64;        // 32 halves = 64 B along K
#pragma unroll
        for (int i = 0; i < 2; i++) {
            uint32_t d = st + (ar + 64 * i) * A_PITCH + acv * 16;
            CP_ASYNC16(d + OFF_AH, pAh[i] + ka);
            CP_ASYNC16(d + OFF_AL, pAl[i] + ka);
        }
#pragma unroll
        for (int t = 0; t < 2; t++) {
            uint32_t d = st + brow[t] * B_PITCH + bcol[t] * 16;
            size_t so = (size_t)(c * 32 + brow[t]) * bstride + bcol[t] * 16;
            CP_ASYNC16(d + OFF_BH, pBh_base + so);
            CP_ASYNC16(d + OFF_BL, pBl_base + so);
        }
        CP_COMMIT();
    };

    float acc[4][4][4];
#pragma unroll
    for (int a = 0; a < 4; a++)
#pragma unroll
        for (int b = 0; b < 4; b++)
#pragma unroll
            for (int r = 0; r < 4; r++) acc[a][b][r] = 0.f;

    issue(0);
    for (int c = 0; c < nch; c++) {
        if (c + 1 < nch) { issue(c + 1); CP_WAIT1(); }
        else             { CP_WAIT0(); }
        __syncthreads();

        const uint32_t st = sm + (c & 1) * STAGE;
#pragma unroll
        for (int ks = 0; ks < 2; ks++) {
            uint32_t ah[4][4], al[4][4];
            const uint32_t arow = wm + (lane & 15);
            const uint32_t acol = ((lane >> 4) * 8 + ks * 16) * 2;
#pragma unroll
            for (int mf = 0; mf < 4; mf++) {
                uint32_t addr = st + (arow + mf * 16) * A_PITCH + acol;
                ldsm_x4(addr + OFF_AH, ah[mf][0], ah[mf][1], ah[mf][2], ah[mf][3]);
                ldsm_x4(addr + OFF_AL, al[mf][0], al[mf][1], al[mf][2], al[mf][3]);
            }
            uint32_t bh[4][2], bl[4][2];
            const uint32_t brw = ks * 16 + (lane & 15);
            const uint32_t bco = (wn + ((lane >> 4) * 8)) * 2;
#pragma unroll
            for (int p = 0; p < 2; p++) {
                uint32_t addr = st + brw * B_PITCH + bco + p * 32;
                ldsm_x4_t(addr + OFF_BH, bh[2 * p][0], bh[2 * p][1], bh[2 * p + 1][0], bh[2 * p + 1][1]);
                ldsm_x4_t(addr + OFF_BL, bl[2 * p][0], bl[2 * p][1], bl[2 * p + 1][0], bl[2 * p + 1][1]);
            }
#pragma unroll
            for (int mf = 0; mf < 4; mf++)
#pragma unroll
                for (int nb = 0; nb < 4; nb++) {
                    float* d = acc[mf][nb];
                    mma_bf16(d[0], d[1], d[2], d[3],
                             ah[mf][0], ah[mf][1], ah[mf][2], ah[mf][3], bh[nb][0], bh[nb][1]);
                    mma_bf16(d[0], d[1], d[2], d[3],
                             ah[mf][0], ah[mf][1], ah[mf][2], ah[mf][3], bl[nb][0], bl[nb][1]);
                    mma_bf16(d[0], d[1], d[2], d[3],
                             al[mf][0], al[mf][1], al[mf][2], al[mf][3], bh[nb][0], bh[nb][1]);
                }
        }
        __syncthreads();
    }

    // ---- epilogue ----
    const float* bp = bias + (size_t)e * N + n0;
#pragma unroll
    for (int mf = 0; mf < 4; mf++)
#pragma unroll
        for (int nb = 0; nb < 4; nb++) {
            const int c  = wn + nb * 8 + (lane & 3) * 2;
            const float b0 = bp[c], b1 = bp[c + 1];
#pragma unroll
            for (int half = 0; half < 2; half++) {
                const int r = wm + mf * 16 + (lane >> 2) + half * 8;
                if (r < rows) {
                    float f0 = acc[mf][nb][half * 2]     + b0;
                    float f1 = acc[mf][nb][half * 2 + 1] + b1;
                    if (RELU) { f0 = fmaxf(f0, 0.f); f1 = fmaxf(f1, 0.f); }
                    const size_t grow = (size_t)(off + m0 + r);
                    const size_t o = grow * N + n0 + c;
                    if (OUT_SPLIT) {
                        __nv_bfloat16 h0 = __float2bfloat16_rn(f0);
                        __nv_bfloat16 h1 = __float2bfloat16_rn(f1);
                        __nv_bfloat16 l0 = __float2bfloat16_rn(f0 - __bfloat162float(h0));
                        __nv_bfloat16 l1 = __float2bfloat16_rn(f1 - __bfloat162float(h1));
                        __nv_bfloat162 hp = {h0, h1}, lp = {l0, l1};
                        *reinterpret_cast<__nv_bfloat162*>(Ch + o) = hp;
                        *reinterpret_cast<__nv_bfloat162*>(Cl + o) = lp;
                    } else {
                        float2 v = {f0, f1};
                        *reinterpret_cast<float2*>(Cf + o) = v;
                    }
                }
            }
        }
}

// out[t] = w0*y[row0] + w1*y[row1]
__global__ void combine_kernel(float* __restrict__ out) {
    int t = blockIdx.x;
    float w0 = g_gw[2 * t], w1 = g_gw[2 * t + 1];
    const float4* y0 = reinterpret_cast<const float4*>(g_y + (size_t)g_rowof[2 * t]     * D_MODEL);
    const float4* y1 = reinterpret_cast<const float4*>(g_y + (size_t)g_rowof[2 * t + 1] * D_MODEL);
    float4* o = reinterpret_cast<float4*>(out + (size_t)t * D_MODEL);
    int i = threadIdx.x;
    float4 a = y0[i], b = y1[i];
    float4 r;
    r.x = w0 * a.x + w1 * b.x;
    r.y = w0 * a.y + w1 * b.y;
    r.z = w0 * a.z + w1 * b.z;
    r.w = w0 * a.w + w1 * b.w;
    o[i] = r;
}

// ---------------- launch ----------------
extern "C" void kernel_launch(void* const* d_in, const int* in_sizes, int n_in,
                              void* d_out, int out_size) {
    const float* x  = (const float*)d_in[0];
    const float* Wg = (const float*)d_in[1];
    const float* W1 = (const float*)d_in[2];
    const float* b1 = (const float*)d_in[3];
    const float* W2 = (const float*)d_in[4];
    const float* b2 = (const float*)d_in[5];
    float* out = (float*)d_out;

    const int T = in_sizes[0] / D_MODEL;   // 4096

    __nv_bfloat16 *xh, *xl, *w1h, *w1l, *w2h, *w2l, *hh, *hl;
    float* ybuf;
    cudaGetSymbolAddress((void**)&xh,  g_xh);
    cudaGetSymbolAddress((void**)&xl,  g_xl);
    cudaGetSymbolAddress((void**)&w1h, g_w1h);
    cudaGetSymbolAddress((void**)&w1l, g_w1l);
    cudaGetSymbolAddress((void**)&w2h, g_w2h);
    cudaGetSymbolAddress((void**)&w2l, g_w2l);
    cudaGetSymbolAddress((void**)&hh,  g_hh);
    cudaGetSymbolAddress((void**)&hl,  g_hl);
    cudaGetSymbolAddress((void**)&ybuf, g_y);

    cudaFuncSetAttribute(mma_gemm<true, true, true>,
                         cudaFuncAttributeMaxDynamicSharedMemorySize, SMEM_SZ);
    cudaFuncSetAttribute(mma_gemm<false, false, false>,
                         cudaFuncAttributeMaxDynamicSharedMemorySize, SMEM_SZ);

    zero_kernel<<<1, 32>>>();
    gate_kernel<<<(T * 32 + 255) / 256, 256>>>(x, Wg, T);
    route_kernel<<<1, 256>>>(T);

    size_t nx = (size_t)T * D_MODEL;
    size_t nw = (size_t)N_EXP * D_MODEL * D_FF;
    split_kernel<<<(unsigned)((nx / 4 + 255) / 256), 256>>>(x,  xh,  xl,  nx);
    split_kernel<<<(unsigned)((nw / 4 + 255) / 256), 256>>>(W1, w1h, w1l, nw);
    split_kernel<<<(unsigned)((nw / 4 + 255) / 256), 256>>>(W2, w2h, w2l, nw);

    // GEMM1: h = relu(x @ W1 + b1), split bf16 out
    mma_gemm<true, true, true><<<dim3(D_FF / 128, MAX_T / 128, N_EXP), 256, SMEM_SZ>>>(
        xh, xl, w1h, w1l, b1, nullptr, hh, hl, D_MODEL, D_FF);
    // GEMM2: y = h @ W2 + b2, fp32 out
    mma_gemm<false, false, false><<<dim3(D_MODEL / 128, MAX_T / 128, N_EXP), 256, SMEM_SZ>>>(
        hh, hl, w2h, w2l, b2, ybuf, nullptr, nullptr, D_FF, D_MODEL);

    combine_kernel<<<T, 256>>>(out);
}

// round 6
// speedup vs baseline: 2.8467x; 1.1521x over previous
#include <cuda_runtime.h>
#include <cuda_bf16.h>
#include <cstdint>

#define D_MODEL 1024
#define D_FF    4096
#define N_EXP   8
#define TOPK    2
#define MAX_T   4096
#define MAX_ROWS (MAX_T * TOPK)

// ---------------- scratch (device globals; no allocation allowed) ----------------
__device__ float g_gw[MAX_T * TOPK];
__device__ int   g_geid[MAX_T * TOPK];
__device__ int   g_rowof[MAX_T * TOPK];
__device__ int   g_tok[MAX_ROWS];
__device__ int   g_cnt[N_EXP];
__device__ int   g_off[N_EXP];
__device__ int   g_pos[N_EXP];

__device__ __nv_bfloat16 g_xh[(size_t)MAX_T * D_MODEL];
__device__ __nv_bfloat16 g_xl[(size_t)MAX_T * D_MODEL];
__device__ __nv_bfloat16 g_w1h[(size_t)N_EXP * D_MODEL * D_FF];
__device__ __nv_bfloat16 g_w1l[(size_t)N_EXP * D_MODEL * D_FF];
__device__ __nv_bfloat16 g_w2h[(size_t)N_EXP * D_FF * D_MODEL];
__device__ __nv_bfloat16 g_w2l[(size_t)N_EXP * D_FF * D_MODEL];
__device__ __nv_bfloat16 g_hh[(size_t)MAX_ROWS * D_FF];
__device__ __nv_bfloat16 g_hl[(size_t)MAX_ROWS * D_FF];
__device__ float g_y[(size_t)MAX_ROWS * D_MODEL];

// ---------------- PTX helpers ----------------
__device__ __forceinline__ uint32_t smem_u32(const void* p) {
    uint32_t a;
    asm("{ .reg .u64 t; cvta.to.shared.u64 t, %1; cvt.u32.u64 %0, t; }" : "=r"(a) : "l"(p));
    return a;
}
#define CP_ASYNC16(dst, src) \
    asm volatile("cp.async.cg.shared.global [%0], [%1], 16;" :: "r"(dst), "l"(src))
#define CP_COMMIT() asm volatile("cp.async.commit_group;" ::: "memory")
#define CP_WAIT1()  asm volatile("cp.async.wait_group 1;" ::: "memory")
#define CP_WAIT0()  asm volatile("cp.async.wait_group 0;" ::: "memory")

__device__ __forceinline__ void ldsm_x4(uint32_t a, uint32_t& r0, uint32_t& r1, uint32_t& r2, uint32_t& r3) {
    asm volatile("ldmatrix.sync.aligned.m8n8.x4.shared.b16 {%0,%1,%2,%3}, [%4];"
                 : "=r"(r0), "=r"(r1), "=r"(r2), "=r"(r3) : "r"(a));
}
__device__ __forceinline__ void ldsm_x4_t(uint32_t a, uint32_t& r0, uint32_t& r1, uint32_t& r2, uint32_t& r3) {
    asm volatile("ldmatrix.sync.aligned.m8n8.x4.trans.shared.b16 {%0,%1,%2,%3}, [%4];"
                 : "=r"(r0), "=r"(r1), "=r"(r2), "=r"(r3) : "r"(a));
}
__device__ __forceinline__ void mma_bf16(float& d0, float& d1, float& d2, float& d3,
                                         uint32_t a0, uint32_t a1, uint32_t a2, uint32_t a3,
                                         uint32_t b0, uint32_t b1) {
    asm volatile("mma.sync.aligned.m16n8k16.row.col.f32.bf16.bf16.f32 "
                 "{%0,%1,%2,%3},{%4,%5,%6,%7},{%8,%9},{%0,%1,%2,%3};"
                 : "+f"(d0), "+f"(d1), "+f"(d2), "+f"(d3)
                 : "r"(a0), "r"(a1), "r"(a2), "r"(a3), "r"(b0), "r"(b1));
}

// ---------------- small kernels ----------------
__global__ void zero_kernel() {
    int i = threadIdx.x;
    if (i < N_EXP) { g_cnt[i] = 0; g_pos[i] = 0; }
}

__global__ void gate_kernel(const float* __restrict__ x,
                            const float* __restrict__ Wg, int T) {
    int gwarp = (blockIdx.x * blockDim.x + threadIdx.x) >> 5;
    int lane  = threadIdx.x & 31;
    if (gwarp >= T) return;
    const float* xr = x + (size_t)gwarp * D_MODEL;
    float acc[N_EXP];
#pragma unroll
    for (int e = 0; e < N_EXP; e++) acc[e] = 0.f;
    for (int d = lane; d < D_MODEL; d += 32) {
        float xv = xr[d];
        const float* wr = Wg + d * N_EXP;
#pragma unroll
        for (int e = 0; e < N_EXP; e++) acc[e] += xv * wr[e];
    }
#pragma unroll
    for (int e = 0; e < N_EXP; e++)
#pragma unroll
        for (int o = 16; o > 0; o >>= 1)
            acc[e] += __shfl_xor_sync(0xFFFFFFFFu, acc[e], o);
    if (lane == 0) {
        int e0 = 0;
#pragma unroll
        for (int e = 1; e < N_EXP; e++) if (acc[e] > acc[e0]) e0 = e;
        int e1 = -1;
#pragma unroll
        for (int e = 0; e < N_EXP; e++) {
            if (e == e0) continue;
            if (e1 < 0 || acc[e] > acc[e1]) e1 = e;
        }
        float l0 = acc[e0], l1 = acc[e1];
        float z1 = __expf(l1 - l0);
        float s  = 1.f + z1;
        g_gw[2 * gwarp]     = 1.f / s;
        g_gw[2 * gwarp + 1] = z1  / s;
        g_geid[2 * gwarp]     = e0;
        g_geid[2 * gwarp + 1] = e1;
        atomicAdd(&g_cnt[e0], 1);
        atomicAdd(&g_cnt[e1], 1);
    }
}

__global__ void route_kernel(int T) {
    if (threadIdx.x == 0) {
        int s = 0;
#pragma unroll
        for (int e = 0; e < N_EXP; e++) { g_off[e] = s; s += g_cnt[e]; }
    }
    __syncthreads();
    int A = T * TOPK;
    for (int a = threadIdx.x; a < A; a += blockDim.x) {
        int e = g_geid[a];
        int p = atomicAdd(&g_pos[e], 1);
        int r = g_off[e] + p;
        g_rowof[a] = r;
        g_tok[r]   = a >> 1;
    }
}

// fp32 -> bf16 hi/lo split; 8 elements/thread, 16B stores
__global__ void split_kernel(const float* __restrict__ in,
                             __nv_bfloat16* __restrict__ oh,
                             __nv_bfloat16* __restrict__ ol, size_t n) {
    size_t i = ((size_t)blockIdx.x * blockDim.x + threadIdx.x) * 8;
    if (i >= n) return;
    float4 v0 = *reinterpret_cast<const float4*>(in + i);
    float4 v1 = *reinterpret_cast<const float4*>(in + i + 4);
    float f[8] = {v0.x, v0.y, v0.z, v0.w, v1.x, v1.y, v1.z, v1.w};
    __nv_bfloat162 hp[4], lp[4];
#pragma unroll
    for (int j = 0; j < 4; j++) {
        __nv_bfloat16 h0 = __float2bfloat16_rn(f[2 * j]);
        __nv_bfloat16 h1 = __float2bfloat16_rn(f[2 * j + 1]);
        __nv_bfloat16 l0 = __float2bfloat16_rn(f[2 * j]     - __bfloat162float(h0));
        __nv_bfloat16 l1 = __float2bfloat16_rn(f[2 * j + 1] - __bfloat162float(h1));
        hp[j] = {h0, h1};
        lp[j] = {l0, l1};
    }
    *reinterpret_cast<uint4*>(oh + i) = *reinterpret_cast<uint4*>(hp);
    *reinterpret_cast<uint4*>(ol + i) = *reinterpret_cast<uint4*>(lp);
}

// ---------------- HMMA grouped GEMM ----------------
// BM=128, BN=128, BK=32. 256 threads = 8 warps (2 M x 4 N), warp tile 64x32.
#define A_PITCH   80
#define B_PITCH   272
#define A_BYTES   (128 * A_PITCH)          // 10240
#define B_BYTES   (32 * B_PITCH)           // 8704
#define OFF_AH    0
#define OFF_AL    A_BYTES
#define OFF_BH    (2 * A_BYTES)
#define OFF_BL    (2 * A_BYTES + B_BYTES)
#define STAGE     (2 * A_BYTES + 2 * B_BYTES)   // 37888
#define SMEM_SZ   (2 * STAGE)                   // 75776 (2 CTAs/SM fit in 228KB)

template <bool GATHER, bool RELU, bool OUT_SPLIT>
__global__ void __launch_bounds__(256, 2)
mma_gemm(const __nv_bfloat16* __restrict__ Ah_g, const __nv_bfloat16* __restrict__ Al_g,
         const __nv_bfloat16* __restrict__ Bh_g, const __nv_bfloat16* __restrict__ Bl_g,
         const float* __restrict__ bias,
         float* __restrict__ Cf,
         __nv_bfloat16* __restrict__ Ch, __nv_bfloat16* __restrict__ Cl,
         int K, int N) {
    const int e   = blockIdx.z;
    const int cnt = g_cnt[e];
    const int m0  = blockIdx.y * 128;
    if (m0 >= cnt) return;
    const int off  = g_off[e];
    const int n0   = blockIdx.x * 128;
    const int rows = min(128, cnt - m0);

    extern __shared__ uint8_t smem[];
    const uint32_t sm = smem_u32(smem);

    const int tid  = threadIdx.x;
    const int wid  = tid >> 5;
    const int lane = tid & 31;
    const int wm   = (wid >> 2) * 64;
    const int wn   = (wid & 3) * 32;

    // A source: 2 rows/thread, 16B chunk acv
    const int ar   = tid >> 2;
    const int acv  = tid & 3;
    const char *pAh[2], *pAl[2];
#pragma unroll
    for (int i = 0; i < 2; i++) {
        int r  = ar + 64 * i;
        int mr = min(r, rows - 1);
        int gr = off + m0 + mr;
        size_t srow = GATHER ? (size_t)g_tok[gr] : (size_t)gr;
        pAh[i] = (const char*)(Ah_g + srow * K) + acv * 16;
        pAl[i] = (const char*)(Al_g + srow * K) + acv * 16;
    }
    // B source: 2 chunks/thread over 32 rows x 16 chunks
    const size_t ebase = (size_t)e * K * N;
    const char* pBh_base = (const char*)(Bh_g + ebase + n0);
    const char* pBl_base = (const char*)(Bl_g + ebase + n0);
    const size_t bstride = (size_t)N * 2;
    int brow[2], bcol[2];
#pragma unroll
    for (int t = 0; t < 2; t++) {
        int idx = tid + 256 * t;
        brow[t] = idx >> 4;
        bcol[t] = idx & 15;
    }

    const int nch = K >> 5;

    auto issue = [&](int c) {
        const uint32_t st = sm + (c & 1) * STAGE;
        const size_t ka = (size_t)c * 64;
#pragma unroll
        for (int i = 0; i < 2; i++) {
            uint32_t d = st + (ar + 64 * i) * A_PITCH + acv * 16;
            CP_ASYNC16(d + OFF_AH, pAh[i] + ka);
            CP_ASYNC16(d + OFF_AL, pAl[i] + ka);
        }
#pragma unroll
        for (int t = 0; t < 2; t++) {
            uint32_t d = st + brow[t] * B_PITCH + bcol[t] * 16;
            size_t so = (size_t)(c * 32 + brow[t]) * bstride + bcol[t] * 16;
            CP_ASYNC16(d + OFF_BH, pBh_base + so);
            CP_ASYNC16(d + OFF_BL, pBl_base + so);
        }
        CP_COMMIT();
    };

    float acc[4][4][4];
#pragma unroll
    for (int a = 0; a < 4; a++)
#pragma unroll
        for (int b = 0; b < 4; b++)
#pragma unroll
            for (int r = 0; r < 4; r++) acc[a][b][r] = 0.f;

    issue(0);
    for (int c = 0; c < nch; c++) {
        if (c + 1 < nch) { issue(c + 1); CP_WAIT1(); }
        else             { CP_WAIT0(); }
        __syncthreads();

        const uint32_t st = sm + (c & 1) * STAGE;
#pragma unroll
        for (int ks = 0; ks < 2; ks++) {
            // B fragments first (reused by all mf) -- 16 regs live
            uint32_t bh[4][2], bl[4][2];
            const uint32_t brw = ks * 16 + (lane & 15);
            const uint32_t bco = (wn + ((lane >> 4) * 8)) * 2;
#pragma unroll
            for (int p = 0; p < 2; p++) {
                uint32_t addr = st + brw * B_PITCH + bco + p * 32;
                ldsm_x4_t(addr + OFF_BH, bh[2 * p][0], bh[2 * p][1], bh[2 * p + 1][0], bh[2 * p + 1][1]);
                ldsm_x4_t(addr + OFF_BL, bl[2 * p][0], bl[2 * p][1], bl[2 * p + 1][0], bl[2 * p + 1][1]);
            }
            // A fragments per-mf just in time -- 8 regs live
            const uint32_t arow = wm + (lane & 15);
            const uint32_t acol = ((lane >> 4) * 8 + ks * 16) * 2;
#pragma unroll
            for (int mf = 0; mf < 4; mf++) {
                uint32_t ah[4], al[4];
                uint32_t addr = st + (arow + mf * 16) * A_PITCH + acol;
                ldsm_x4(addr + OFF_AH, ah[0], ah[1], ah[2], ah[3]);
                ldsm_x4(addr + OFF_AL, al[0], al[1], al[2], al[3]);
#pragma unroll
                for (int nb = 0; nb < 4; nb++) {
                    float* d = acc[mf][nb];
                    mma_bf16(d[0], d[1], d[2], d[3],
                             ah[0], ah[1], ah[2], ah[3], bh[nb][0], bh[nb][1]);
                    mma_bf16(d[0], d[1], d[2], d[3],
                             ah[0], ah[1], ah[2], ah[3], bl[nb][0], bl[nb][1]);
                    mma_bf16(d[0], d[1], d[2], d[3],
                             al[0], al[1], al[2], al[3], bh[nb][0], bh[nb][1]);
                }
            }
        }
        __syncthreads();
    }

    // ---- epilogue ----
    const float* bp = bias + (size_t)e * N + n0;
#pragma unroll
    for (int mf = 0; mf < 4; mf++)
#pragma unroll
        for (int nb = 0; nb < 4; nb++) {
            const int c  = wn + nb * 8 + (lane & 3) * 2;
            const float b0 = bp[c], b1 = bp[c + 1];
#pragma unroll
            for (int half = 0; half < 2; half++) {
                const int r = wm + mf * 16 + (lane >> 2) + half * 8;
                if (r < rows) {
                    float f0 = acc[mf][nb][half * 2]     + b0;
                    float f1 = acc[mf][nb][half * 2 + 1] + b1;
                    if (RELU) { f0 = fmaxf(f0, 0.f); f1 = fmaxf(f1, 0.f); }
                    const size_t grow = (size_t)(off + m0 + r);
                    const size_t o = grow * N + n0 + c;
                    if (OUT_SPLIT) {
                        __nv_bfloat16 h0 = __float2bfloat16_rn(f0);
                        __nv_bfloat16 h1 = __float2bfloat16_rn(f1);
                        __nv_bfloat16 l0 = __float2bfloat16_rn(f0 - __bfloat162float(h0));
                        __nv_bfloat16 l1 = __float2bfloat16_rn(f1 - __bfloat162float(h1));
                        __nv_bfloat162 hp = {h0, h1}, lp = {l0, l1};
                        *reinterpret_cast<__nv_bfloat162*>(Ch + o) = hp;
                        *reinterpret_cast<__nv_bfloat162*>(Cl + o) = lp;
                    } else {
                        float2 v = {f0, f1};
                        *reinterpret_cast<float2*>(Cf + o) = v;
                    }
                }
            }
        }
}

// out[t] = w0*y[row0] + w1*y[row1]
__global__ void combine_kernel(float* __restrict__ out) {
    int t = blockIdx.x;
    float w0 = g_gw[2 * t], w1 = g_gw[2 * t + 1];
    const float4* y0 = reinterpret_cast<const float4*>(g_y + (size_t)g_rowof[2 * t]     * D_MODEL);
    const float4* y1 = reinterpret_cast<const float4*>(g_y + (size_t)g_rowof[2 * t + 1] * D_MODEL);
    float4* o = reinterpret_cast<float4*>(out + (size_t)t * D_MODEL);
    int i = threadIdx.x;
    float4 a = y0[i], b = y1[i];
    float4 r;
    r.x = w0 * a.x + w1 * b.x;
    r.y = w0 * a.y + w1 * b.y;
    r.z = w0 * a.z + w1 * b.z;
    r.w = w0 * a.w + w1 * b.w;
    o[i] = r;
}

// ---------------- launch ----------------
extern "C" void kernel_launch(void* const* d_in, const int* in_sizes, int n_in,
                              void* d_out, int out_size) {
    const float* x  = (const float*)d_in[0];
    const float* Wg = (const float*)d_in[1];
    const float* W1 = (const float*)d_in[2];
    const float* b1 = (const float*)d_in[3];
    const float* W2 = (const float*)d_in[4];
    const float* b2 = (const float*)d_in[5];
    float* out = (float*)d_out;

    const int T = in_sizes[0] / D_MODEL;   // 4096

    __nv_bfloat16 *xh, *xl, *w1h, *w1l, *w2h, *w2l, *hh, *hl;
    float* ybuf;
    cudaGetSymbolAddress((void**)&xh,  g_xh);
    cudaGetSymbolAddress((void**)&xl,  g_xl);
    cudaGetSymbolAddress((void**)&w1h, g_w1h);
    cudaGetSymbolAddress((void**)&w1l, g_w1l);
    cudaGetSymbolAddress((void**)&w2h, g_w2h);
    cudaGetSymbolAddress((void**)&w2l, g_w2l);
    cudaGetSymbolAddress((void**)&hh,  g_hh);
    cudaGetSymbolAddress((void**)&hl,  g_hl);
    cudaGetSymbolAddress((void**)&ybuf, g_y);

    cudaFuncSetAttribute(mma_gemm<true, true, true>,
                         cudaFuncAttributeMaxDynamicSharedMemorySize, SMEM_SZ);
    cudaFuncSetAttribute(mma_gemm<false, false, false>,
                         cudaFuncAttributeMaxDynamicSharedMemorySize, SMEM_SZ);

    zero_kernel<<<1, 32>>>();
    gate_kernel<<<(T * 32 + 255) / 256, 256>>>(x, Wg, T);
    route_kernel<<<1, 256>>>(T);

    size_t nx = (size_t)T * D_MODEL;
    size_t nw = (size_t)N_EXP * D_MODEL * D_FF;
    split_kernel<<<(unsigned)((nx / 8 + 255) / 256), 256>>>(x,  xh,  xl,  nx);
    split_kernel<<<(unsigned)((nw / 8 + 255) / 256), 256>>>(W1, w1h, w1l, nw);
    split_kernel<<<(unsigned)((nw / 8 + 255) / 256), 256>>>(W2, w2h, w2l, nw);

    // GEMM1: h = relu(x @ W1 + b1), split bf16 out
    mma_gemm<true, true, true><<<dim3(D_FF / 128, MAX_T / 128, N_EXP), 256, SMEM_SZ>>>(
        xh, xl, w1h, w1l, b1, nullptr, hh, hl, D_MODEL, D_FF);
    // GEMM2: y = h @ W2 + b2, fp32 out
    mma_gemm<false, false, false><<<dim3(D_MODEL / 128, MAX_T / 128, N_EXP), 256, SMEM_SZ>>>(
        hh, hl, w2h, w2l, b2, ybuf, nullptr, nullptr, D_FF, D_MODEL);

    combine_kernel<<<T, 256>>>(out);
}

// round 7
// speedup vs baseline: 3.7722x; 1.3251x over previous
#include <cuda_runtime.h>
#include <cuda_fp16.h>
#include <cstdint>

#define D_MODEL 1024
#define D_FF    4096
#define N_EXP   8
#define TOPK    2
#define MAX_T   4096
#define MAX_ROWS (MAX_T * TOPK)

// ---------------- scratch (device globals; no allocation allowed) ----------------
__device__ float g_gw[MAX_T * TOPK];
__device__ int   g_geid[MAX_T * TOPK];
__device__ int   g_rowof[MAX_T * TOPK];
__device__ int   g_tok[MAX_ROWS];
__device__ int   g_cnt[N_EXP];
__device__ int   g_off[N_EXP];
__device__ int   g_pos[N_EXP];

__device__ __half g_xh[(size_t)MAX_T * D_MODEL];      // x hi
__device__ __half g_xl[(size_t)MAX_T * D_MODEL];      // x lo
__device__ __half g_w1[(size_t)N_EXP * D_MODEL * D_FF];   // W1 fp16 (single)
__device__ __half g_w2[(size_t)N_EXP * D_FF * D_MODEL];   // W2 fp16 (single)
__device__ __half g_hh[(size_t)MAX_ROWS * D_FF];      // h hi
__device__ __half g_hl[(size_t)MAX_ROWS * D_FF];      // h lo
__device__ float g_y[(size_t)MAX_ROWS * D_MODEL];

// ---------------- PTX helpers ----------------
__device__ __forceinline__ uint32_t smem_u32(const void* p) {
    uint32_t a;
    asm("{ .reg .u64 t; cvta.to.shared.u64 t, %1; cvt.u32.u64 %0, t; }" : "=r"(a) : "l"(p));
    return a;
}
#define CP_ASYNC16(dst, src) \
    asm volatile("cp.async.cg.shared.global [%0], [%1], 16;" :: "r"(dst), "l"(src))
#define CP_COMMIT() asm volatile("cp.async.commit_group;" ::: "memory")
#define CP_WAIT1()  asm volatile("cp.async.wait_group 1;" ::: "memory")
#define CP_WAIT0()  asm volatile("cp.async.wait_group 0;" ::: "memory")

__device__ __forceinline__ void ldsm_x4(uint32_t a, uint32_t& r0, uint32_t& r1, uint32_t& r2, uint32_t& r3) {
    asm volatile("ldmatrix.sync.aligned.m8n8.x4.shared.b16 {%0,%1,%2,%3}, [%4];"
                 : "=r"(r0), "=r"(r1), "=r"(r2), "=r"(r3) : "r"(a));
}
__device__ __forceinline__ void ldsm_x4_t(uint32_t a, uint32_t& r0, uint32_t& r1, uint32_t& r2, uint32_t& r3) {
    asm volatile("ldmatrix.sync.aligned.m8n8.x4.trans.shared.b16 {%0,%1,%2,%3}, [%4];"
                 : "=r"(r0), "=r"(r1), "=r"(r2), "=r"(r3) : "r"(a));
}
__device__ __forceinline__ void mma_fp16(float& d0, float& d1, float& d2, float& d3,
                                         uint32_t a0, uint32_t a1, uint32_t a2, uint32_t a3,
                                         uint32_t b0, uint32_t b1) {
    asm volatile("mma.sync.aligned.m16n8k16.row.col.f32.f16.f16.f32 "
                 "{%0,%1,%2,%3},{%4,%5,%6,%7},{%8,%9},{%0,%1,%2,%3};"
                 : "+f"(d0), "+f"(d1), "+f"(d2), "+f"(d3)
                 : "r"(a0), "r"(a1), "r"(a2), "r"(a3), "r"(b0), "r"(b1));
}

// ---------------- small kernels ----------------
__global__ void zero_kernel() {
    int i = threadIdx.x;
    if (i < N_EXP) { g_cnt[i] = 0; g_pos[i] = 0; }
}

__global__ void gate_kernel(const float* __restrict__ x,
                            const float* __restrict__ Wg, int T) {
    int gwarp = (blockIdx.x * blockDim.x + threadIdx.x) >> 5;
    int lane  = threadIdx.x & 31;
    if (gwarp >= T) return;
    const float* xr = x + (size_t)gwarp * D_MODEL;
    float acc[N_EXP];
#pragma unroll
    for (int e = 0; e < N_EXP; e++) acc[e] = 0.f;
    for (int d = lane; d < D_MODEL; d += 32) {
        float xv = xr[d];
        const float* wr = Wg + d * N_EXP;
#pragma unroll
        for (int e = 0; e < N_EXP; e++) acc[e] += xv * wr[e];
    }
#pragma unroll
    for (int e = 0; e < N_EXP; e++)
#pragma unroll
        for (int o = 16; o > 0; o >>= 1)
            acc[e] += __shfl_xor_sync(0xFFFFFFFFu, acc[e], o);
    if (lane == 0) {
        int e0 = 0;
#pragma unroll
        for (int e = 1; e < N_EXP; e++) if (acc[e] > acc[e0]) e0 = e;
        int e1 = -1;
#pragma unroll
        for (int e = 0; e < N_EXP; e++) {
            if (e == e0) continue;
            if (e1 < 0 || acc[e] > acc[e1]) e1 = e;
        }
        float l0 = acc[e0], l1 = acc[e1];
        float z1 = __expf(l1 - l0);
        float s  = 1.f + z1;
        g_gw[2 * gwarp]     = 1.f / s;
        g_gw[2 * gwarp + 1] = z1  / s;
        g_geid[2 * gwarp]     = e0;
        g_geid[2 * gwarp + 1] = e1;
        atomicAdd(&g_cnt[e0], 1);
        atomicAdd(&g_cnt[e1], 1);
    }
}

__global__ void route_kernel(int T) {
    if (threadIdx.x == 0) {
        int s = 0;
#pragma unroll
        for (int e = 0; e < N_EXP; e++) { g_off[e] = s; s += g_cnt[e]; }
    }
    __syncthreads();
    int A = T * TOPK;
    for (int a = threadIdx.x; a < A; a += blockDim.x) {
        int e = g_geid[a];
        int p = atomicAdd(&g_pos[e], 1);
        int r = g_off[e] + p;
        g_rowof[a] = r;
        g_tok[r]   = a >> 1;
    }
}

// fp32 -> fp16 hi/lo split; 8 elems/thread
__global__ void split2_kernel(const float* __restrict__ in,
                              __half* __restrict__ oh,
                              __half* __restrict__ ol, size_t n) {
    size_t i = ((size_t)blockIdx.x * blockDim.x + threadIdx.x) * 8;
    if (i >= n) return;
    float4 v0 = *reinterpret_cast<const float4*>(in + i);
    float4 v1 = *reinterpret_cast<const float4*>(in + i + 4);
    float f[8] = {v0.x, v0.y, v0.z, v0.w, v1.x, v1.y, v1.z, v1.w};
    __half2 hp[4], lp[4];
#pragma unroll
    for (int j = 0; j < 4; j++) {
        __half h0 = __float2half_rn(f[2 * j]);
        __half h1 = __float2half_rn(f[2 * j + 1]);
        __half l0 = __float2half_rn(f[2 * j]     - __half2float(h0));
        __half l1 = __float2half_rn(f[2 * j + 1] - __half2float(h1));
        hp[j] = {h0, h1};
        lp[j] = {l0, l1};
    }
    *reinterpret_cast<uint4*>(oh + i) = *reinterpret_cast<uint4*>(hp);
    *reinterpret_cast<uint4*>(ol + i) = *reinterpret_cast<uint4*>(lp);
}

// fp32 -> fp16 (single); 8 elems/thread
__global__ void conv_kernel(const float* __restrict__ in,
                            __half* __restrict__ o, size_t n) {
    size_t i = ((size_t)blockIdx.x * blockDim.x + threadIdx.x) * 8;
    if (i >= n) return;
    float4 v0 = *reinterpret_cast<const float4*>(in + i);
    float4 v1 = *reinterpret_cast<const float4*>(in + i + 4);
    __half2 p[4];
    p[0] = __floats2half2_rn(v0.x, v0.y);
    p[1] = __floats2half2_rn(v0.z, v0.w);
    p[2] = __floats2half2_rn(v1.x, v1.y);
    p[3] = __floats2half2_rn(v1.z, v1.w);
    *reinterpret_cast<uint4*>(o + i) = *reinterpret_cast<uint4*>(p);
}

// ---------------- HMMA grouped GEMM (fp16, A split 2-pass) ----------------
// BM=128, BN=128, BK=32. 256 threads = 8 warps (2 M x 4 N), warp tile 64x32.
#define A_PITCH   80
#define B_PITCH   272
#define A_BYTES   (128 * A_PITCH)          // 10240
#define B_BYTES   (32 * B_PITCH)           // 8704
#define OFF_AH    0
#define OFF_AL    A_BYTES
#define OFF_B     (2 * A_BYTES)
#define STAGE     (2 * A_BYTES + B_BYTES)  // 29184
#define SMEM_SZ   (2 * STAGE)              // 58368 (2 CTAs/SM)

template <bool GATHER, bool RELU, bool OUT_SPLIT>
__global__ void __launch_bounds__(256, 2)
mma_gemm(const __half* __restrict__ Ah_g, const __half* __restrict__ Al_g,
         const __half* __restrict__ B_g,
         const float* __restrict__ bias,
         float* __restrict__ Cf,
         __half* __restrict__ Ch, __half* __restrict__ Cl,
         int K, int N) {
    const int e   = blockIdx.z;
    const int cnt = g_cnt[e];
    const int m0  = blockIdx.y * 128;
    if (m0 >= cnt) return;
    const int off  = g_off[e];
    const int n0   = blockIdx.x * 128;
    const int rows = min(128, cnt - m0);

    extern __shared__ uint8_t smem[];
    const uint32_t sm = smem_u32(smem);

    const int tid  = threadIdx.x;
    const int wid  = tid >> 5;
    const int lane = tid & 31;
    const int wm   = (wid >> 2) * 64;
    const int wn   = (wid & 3) * 32;

    // A source: 2 rows/thread, 16B chunk acv
    const int ar   = tid >> 2;
    const int acv  = tid & 3;
    const char *pAh[2], *pAl[2];
#pragma unroll
    for (int i = 0; i < 2; i++) {
        int r  = ar + 64 * i;
        int mr = min(r, rows - 1);
        int gr = off + m0 + mr;
        size_t srow = GATHER ? (size_t)g_tok[gr] : (size_t)gr;
        pAh[i] = (const char*)(Ah_g + srow * K) + acv * 16;
        pAl[i] = (const char*)(Al_g + srow * K) + acv * 16;
    }
    // B source: 2 chunks/thread over 32 rows x 16 chunks (single array)
    const size_t ebase = (size_t)e * K * N;
    const char* pB_base = (const char*)(B_g + ebase + n0);
    const size_t bstride = (size_t)N * 2;
    int brow[2], bcol[2];
#pragma unroll
    for (int t = 0; t < 2; t++) {
        int idx = tid + 256 * t;
        brow[t] = idx >> 4;
        bcol[t] = idx & 15;
    }

    const int nch = K >> 5;

    auto issue = [&](int c) {
        const uint32_t st = sm + (c & 1) * STAGE;
        const size_t ka = (size_t)c * 64;
#pragma unroll
        for (int i = 0; i < 2; i++) {
            uint32_t d = st + (ar + 64 * i) * A_PITCH + acv * 16;
            CP_ASYNC16(d + OFF_AH, pAh[i] + ka);
            CP_ASYNC16(d + OFF_AL, pAl[i] + ka);
        }
#pragma unroll
        for (int t = 0; t < 2; t++) {
            uint32_t d = st + brow[t] * B_PITCH + bcol[t] * 16;
            size_t so = (size_t)(c * 32 + brow[t]) * bstride + bcol[t] * 16;
            CP_ASYNC16(d + OFF_B, pB_base + so);
        }
        CP_COMMIT();
    };

    float acc[4][4][4];
#pragma unroll
    for (int a = 0; a < 4; a++)
#pragma unroll
        for (int b = 0; b < 4; b++)
#pragma unroll
            for (int r = 0; r < 4; r++) acc[a][b][r] = 0.f;

    issue(0);
    for (int c = 0; c < nch; c++) {
        if (c + 1 < nch) { issue(c + 1); CP_WAIT1(); }
        else             { CP_WAIT0(); }
        __syncthreads();

        const uint32_t st = sm + (c & 1) * STAGE;
#pragma unroll
        for (int ks = 0; ks < 2; ks++) {
            // B fragments (single precision level, reused by all mf)
            uint32_t bb[4][2];
            const uint32_t brw = ks * 16 + (lane & 15);
            const uint32_t bco = (wn + ((lane >> 4) * 8)) * 2;
#pragma unroll
            for (int p = 0; p < 2; p++) {
                uint32_t addr = st + brw * B_PITCH + bco + p * 32;
                ldsm_x4_t(addr + OFF_B, bb[2 * p][0], bb[2 * p][1], bb[2 * p + 1][0], bb[2 * p + 1][1]);
            }
            // A fragments per-mf just in time (hi + lo)
            const uint32_t arow = wm + (lane & 15);
            const uint32_t acol = ((lane >> 4) * 8 + ks * 16) * 2;
#pragma unroll
            for (int mf = 0; mf < 4; mf++) {
                uint32_t ah[4], al[4];
                uint32_t addr = st + (arow + mf * 16) * A_PITCH + acol;
                ldsm_x4(addr + OFF_AH, ah[0], ah[1], ah[2], ah[3]);
                ldsm_x4(addr + OFF_AL, al[0], al[1], al[2], al[3]);
#pragma unroll
                for (int nb = 0; nb < 4; nb++) {
                    float* d = acc[mf][nb];
                    mma_fp16(d[0], d[1], d[2], d[3],
                             ah[0], ah[1], ah[2], ah[3], bb[nb][0], bb[nb][1]);
                    mma_fp16(d[0], d[1], d[2], d[3],
                             al[0], al[1], al[2], al[3], bb[nb][0], bb[nb][1]);
                }
            }
        }
        __syncthreads();
    }

    // ---- epilogue ----
    const float* bp = bias + (size_t)e * N + n0;
#pragma unroll
    for (int mf = 0; mf < 4; mf++)
#pragma unroll
        for (int nb = 0; nb < 4; nb++) {
            const int c  = wn + nb * 8 + (lane & 3) * 2;
            const float b0 = bp[c], b1 = bp[c + 1];
#pragma unroll
            for (int half = 0; half < 2; half++) {
                const int r = wm + mf * 16 + (lane >> 2) + half * 8;
                if (r < rows) {
                    float f0 = acc[mf][nb][half * 2]     + b0;
                    float f1 = acc[mf][nb][half * 2 + 1] + b1;
                    if (RELU) { f0 = fmaxf(f0, 0.f); f1 = fmaxf(f1, 0.f); }
                    const size_t grow = (size_t)(off + m0 + r);
                    const size_t o = grow * N + n0 + c;
                    if (OUT_SPLIT) {
                        __half h0 = __float2half_rn(f0);
                        __half h1 = __float2half_rn(f1);
                        __half l0 = __float2half_rn(f0 - __half2float(h0));
                        __half l1 = __float2half_rn(f1 - __half2float(h1));
                        __half2 hp = {h0, h1}, lp = {l0, l1};
                        *reinterpret_cast<__half2*>(Ch + o) = hp;
                        *reinterpret_cast<__half2*>(Cl + o) = lp;
                    } else {
                        float2 v = {f0, f1};
                        *reinterpret_cast<float2*>(Cf + o) = v;
                    }
                }
            }
        }
}

// out[t] = w0*y[row0] + w1*y[row1]
__global__ void combine_kernel(float* __restrict__ out) {
    int t = blockIdx.x;
    float w0 = g_gw[2 * t], w1 = g_gw[2 * t + 1];
    const float4* y0 = reinterpret_cast<const float4*>(g_y + (size_t)g_rowof[2 * t]     * D_MODEL);
    const float4* y1 = reinterpret_cast<const float4*>(g_y + (size_t)g_rowof[2 * t + 1] * D_MODEL);
    float4* o = reinterpret_cast<float4*>(out + (size_t)t * D_MODEL);
    int i = threadIdx.x;
    float4 a = y0[i], b = y1[i];
    float4 r;
    r.x = w0 * a.x + w1 * b.x;
    r.y = w0 * a.y + w1 * b.y;
    r.z = w0 * a.z + w1 * b.z;
    r.w = w0 * a.w + w1 * b.w;
    o[i] = r;
}

// ---------------- launch ----------------
extern "C" void kernel_launch(void* const* d_in, const int* in_sizes, int n_in,
                              void* d_out, int out_size) {
    const float* x  = (const float*)d_in[0];
    const float* Wg = (const float*)d_in[1];
    const float* W1 = (const float*)d_in[2];
    const float* b1 = (const float*)d_in[3];
    const float* W2 = (const float*)d_in[4];
    const float* b2 = (const float*)d_in[5];
    float* out = (float*)d_out;

    const int T = in_sizes[0] / D_MODEL;   // 4096

    __half *xh, *xl, *w1, *w2, *hh, *hl;
    float* ybuf;
    cudaGetSymbolAddress((void**)&xh, g_xh);
    cudaGetSymbolAddress((void**)&xl, g_xl);
    cudaGetSymbolAddress((void**)&w1, g_w1);
    cudaGetSymbolAddress((void**)&w2, g_w2);
    cudaGetSymbolAddress((void**)&hh, g_hh);
    cudaGetSymbolAddress((void**)&hl, g_hl);
    cudaGetSymbolAddress((void**)&ybuf, g_y);

    cudaFuncSetAttribute(mma_gemm<true, true, true>,
                         cudaFuncAttributeMaxDynamicSharedMemorySize, SMEM_SZ);
    cudaFuncSetAttribute(mma_gemm<false, false, false>,
                         cudaFuncAttributeMaxDynamicSharedMemorySize, SMEM_SZ);

    zero_kernel<<<1, 32>>>();
    gate_kernel<<<(T * 32 + 255) / 256, 256>>>(x, Wg, T);
    route_kernel<<<1, 256>>>(T);

    size_t nx = (size_t)T * D_MODEL;
    size_t nw = (size_t)N_EXP * D_MODEL * D_FF;
    split2_kernel<<<(unsigned)((nx / 8 + 255) / 256), 256>>>(x, xh, xl, nx);
    conv_kernel<<<(unsigned)((nw / 8 + 255) / 256), 256>>>(W1, w1, nw);
    conv_kernel<<<(unsigned)((nw / 8 + 255) / 256), 256>>>(W2, w2, nw);

    // GEMM1: h = relu(x @ W1 + b1), fp16 hi/lo out
    mma_gemm<true, true, true><<<dim3(D_FF / 128, MAX_T / 128, N_EXP), 256, SMEM_SZ>>>(
        xh, xl, w1, b1, nullptr, hh, hl, D_MODEL, D_FF);
    // GEMM2: y = h @ W2 + b2, fp32 out
    mma_gemm<false, false, false><<<dim3(D_MODEL / 128, MAX_T / 128, N_EXP), 256, SMEM_SZ>>>(
        hh, hl, w2, b2, ybuf, nullptr, nullptr, D_FF, D_MODEL);

    combine_kernel<<<T, 256>>>(out);
}

// round 8
// speedup vs baseline: 5.9825x; 1.5860x over previous
#include <cuda_runtime.h>
#include <cuda_fp16.h>
#include <cstdint>

#define D_MODEL 1024
#define D_FF    4096
#define N_EXP   8
#define TOPK    2
#define MAX_T   4096
#define MAX_ROWS (MAX_T * TOPK)

// ---------------- scratch (device globals; no allocation allowed) ----------------
__device__ float g_gw[MAX_T * TOPK];
__device__ int   g_geid[MAX_T * TOPK];
__device__ int   g_rowof[MAX_T * TOPK];
__device__ int   g_tok[MAX_ROWS];
__device__ int   g_cnt[N_EXP];
__device__ int   g_off[N_EXP];
__device__ int   g_pos[N_EXP];

__device__ __half g_x16[(size_t)MAX_T * D_MODEL];
__device__ __half g_w1[(size_t)N_EXP * D_MODEL * D_FF];
__device__ __half g_w2[(size_t)N_EXP * D_FF * D_MODEL];
__device__ __half g_h16[(size_t)MAX_ROWS * D_FF];
__device__ float g_y[(size_t)MAX_ROWS * D_MODEL];

// ---------------- PTX helpers ----------------
__device__ __forceinline__ uint32_t smem_u32(const void* p) {
    uint32_t a;
    asm("{ .reg .u64 t; cvta.to.shared.u64 t, %1; cvt.u32.u64 %0, t; }" : "=r"(a) : "l"(p));
    return a;
}
#define CP_ASYNC16(dst, src) \
    asm volatile("cp.async.cg.shared.global [%0], [%1], 16;" :: "r"(dst), "l"(src))
#define CP_COMMIT() asm volatile("cp.async.commit_group;" ::: "memory")
#define CP_WAIT1()  asm volatile("cp.async.wait_group 1;" ::: "memory")
#define CP_WAIT0()  asm volatile("cp.async.wait_group 0;" ::: "memory")

__device__ __forceinline__ void ldsm_x4(uint32_t a, uint32_t& r0, uint32_t& r1, uint32_t& r2, uint32_t& r3) {
    asm volatile("ldmatrix.sync.aligned.m8n8.x4.shared.b16 {%0,%1,%2,%3}, [%4];"
                 : "=r"(r0), "=r"(r1), "=r"(r2), "=r"(r3) : "r"(a));
}
__device__ __forceinline__ void ldsm_x4_t(uint32_t a, uint32_t& r0, uint32_t& r1, uint32_t& r2, uint32_t& r3) {
    asm volatile("ldmatrix.sync.aligned.m8n8.x4.trans.shared.b16 {%0,%1,%2,%3}, [%4];"
                 : "=r"(r0), "=r"(r1), "=r"(r2), "=r"(r3) : "r"(a));
}
__device__ __forceinline__ void mma_fp16(float& d0, float& d1, float& d2, float& d3,
                                         uint32_t a0, uint32_t a1, uint32_t a2, uint32_t a3,
                                         uint32_t b0, uint32_t b1) {
    asm volatile("mma.sync.aligned.m16n8k16.row.col.f32.f16.f16.f32 "
                 "{%0,%1,%2,%3},{%4,%5,%6,%7},{%8,%9},{%0,%1,%2,%3};"
                 : "+f"(d0), "+f"(d1), "+f"(d2), "+f"(d3)
                 : "r"(a0), "r"(a1), "r"(a2), "r"(a3), "r"(b0), "r"(b1));
}

// ---------------- small kernels ----------------
__global__ void zero_kernel() {
    int i = threadIdx.x;
    if (i < N_EXP) { g_cnt[i] = 0; g_pos[i] = 0; }
}

__global__ void gate_kernel(const float* __restrict__ x,
                            const float* __restrict__ Wg, int T) {
    int gwarp = (blockIdx.x * blockDim.x + threadIdx.x) >> 5;
    int lane  = threadIdx.x & 31;
    if (gwarp >= T) return;
    const float* xr = x + (size_t)gwarp * D_MODEL;
    float acc[N_EXP];
#pragma unroll
    for (int e = 0; e < N_EXP; e++) acc[e] = 0.f;
    for (int d = lane; d < D_MODEL; d += 32) {
        float xv = xr[d];
        const float* wr = Wg + d * N_EXP;
#pragma unroll
        for (int e = 0; e < N_EXP; e++) acc[e] += xv * wr[e];
    }
#pragma unroll
    for (int e = 0; e < N_EXP; e++)
#pragma unroll
        for (int o = 16; o > 0; o >>= 1)
            acc[e] += __shfl_xor_sync(0xFFFFFFFFu, acc[e], o);
    if (lane == 0) {
        int e0 = 0;
#pragma unroll
        for (int e = 1; e < N_EXP; e++) if (acc[e] > acc[e0]) e0 = e;
        int e1 = -1;
#pragma unroll
        for (int e = 0; e < N_EXP; e++) {
            if (e == e0) continue;
            if (e1 < 0 || acc[e] > acc[e1]) e1 = e;
        }
        float l0 = acc[e0], l1 = acc[e1];
        float z1 = __expf(l1 - l0);
        float s  = 1.f + z1;
        g_gw[2 * gwarp]     = 1.f / s;
        g_gw[2 * gwarp + 1] = z1  / s;
        g_geid[2 * gwarp]     = e0;
        g_geid[2 * gwarp + 1] = e1;
        atomicAdd(&g_cnt[e0], 1);
        atomicAdd(&g_cnt[e1], 1);
    }
}

__global__ void route_kernel(int T) {
    if (threadIdx.x == 0) {
        int s = 0;
#pragma unroll
        for (int e = 0; e < N_EXP; e++) { g_off[e] = s; s += g_cnt[e]; }
    }
    __syncthreads();
    int A = T * TOPK;
    for (int a = threadIdx.x; a < A; a += blockDim.x) {
        int e = g_geid[a];
        int p = atomicAdd(&g_pos[e], 1);
        int r = g_off[e] + p;
        g_rowof[a] = r;
        g_tok[r]   = a >> 1;
    }
}

// fp32 -> fp16; 8 elems/thread
__global__ void conv_kernel(const float* __restrict__ in,
                            __half* __restrict__ o, size_t n) {
    size_t i = ((size_t)blockIdx.x * blockDim.x + threadIdx.x) * 8;
    if (i >= n) return;
    float4 v0 = *reinterpret_cast<const float4*>(in + i);
    float4 v1 = *reinterpret_cast<const float4*>(in + i + 4);
    __half2 p[4];
    p[0] = __floats2half2_rn(v0.x, v0.y);
    p[1] = __floats2half2_rn(v0.z, v0.w);
    p[2] = __floats2half2_rn(v1.x, v1.y);
    p[3] = __floats2half2_rn(v1.z, v1.w);
    *reinterpret_cast<uint4*>(o + i) = *reinterpret_cast<uint4*>(p);
}

// ---------------- HMMA grouped GEMM (fp16, single-pass) ----------------
// BM=128, BN=128, BK=32. 256 threads = 8 warps (2 M x 4 N), warp tile 64x32.
#define A_PITCH   80
#define B_PITCH   272
#define A_BYTES   (128 * A_PITCH)          // 10240
#define B_BYTES   (32 * B_PITCH)           // 8704
#define OFF_A     0
#define OFF_B     A_BYTES
#define STAGE     (A_BYTES + B_BYTES)      // 18944
#define SMEM_SZ   (2 * STAGE)              // 37888 (2 CTAs/SM easily)

template <bool GATHER, bool RELU, bool OUT_HALF>
__global__ void __launch_bounds__(256, 2)
mma_gemm(const __half* __restrict__ A_g,
         const __half* __restrict__ B_g,
         const float* __restrict__ bias,
         float* __restrict__ Cf,
         __half* __restrict__ Ch,
         int K, int N) {
    const int e   = blockIdx.z;
    const int cnt = g_cnt[e];
    const int m0  = blockIdx.y * 128;
    if (m0 >= cnt) return;
    const int off  = g_off[e];
    const int n0   = blockIdx.x * 128;
    const int rows = min(128, cnt - m0);

    extern __shared__ uint8_t smem[];
    const uint32_t sm = smem_u32(smem);

    const int tid  = threadIdx.x;
    const int wid  = tid >> 5;
    const int lane = tid & 31;
    const int wm   = (wid >> 2) * 64;
    const int wn   = (wid & 3) * 32;

    // A source: 2 rows/thread, 16B chunk acv
    const int ar   = tid >> 2;
    const int acv  = tid & 3;
    const char *pA[2];
#pragma unroll
    for (int i = 0; i < 2; i++) {
        int r  = ar + 64 * i;
        int mr = min(r, rows - 1);
        int gr = off + m0 + mr;
        size_t srow = GATHER ? (size_t)g_tok[gr] : (size_t)gr;
        pA[i] = (const char*)(A_g + srow * K) + acv * 16;
    }
    // B source: 2 chunks/thread over 32 rows x 16 chunks
    const size_t ebase = (size_t)e * K * N;
    const char* pB_base = (const char*)(B_g + ebase + n0);
    const size_t bstride = (size_t)N * 2;
    int brow[2], bcol[2];
#pragma unroll
    for (int t = 0; t < 2; t++) {
        int idx = tid + 256 * t;
        brow[t] = idx >> 4;
        bcol[t] = idx & 15;
    }

    const int nch = K >> 5;

    auto issue = [&](int c) {
        const uint32_t st = sm + (c & 1) * STAGE;
        const size_t ka = (size_t)c * 64;
#pragma unroll
        for (int i = 0; i < 2; i++) {
            uint32_t d = st + (ar + 64 * i) * A_PITCH + acv * 16;
            CP_ASYNC16(d + OFF_A, pA[i] + ka);
        }
#pragma unroll
        for (int t = 0; t < 2; t++) {
            uint32_t d = st + brow[t] * B_PITCH + bcol[t] * 16;
            size_t so = (size_t)(c * 32 + brow[t]) * bstride + bcol[t] * 16;
            CP_ASYNC16(d + OFF_B, pB_base + so);
        }
        CP_COMMIT();
    };

    float acc[4][4][4];
#pragma unroll
    for (int a = 0; a < 4; a++)
#pragma unroll
        for (int b = 0; b < 4; b++)
#pragma unroll
            for (int r = 0; r < 4; r++) acc[a][b][r] = 0.f;

    issue(0);
    for (int c = 0; c < nch; c++) {
        if (c + 1 < nch) { issue(c + 1); CP_WAIT1(); }
        else             { CP_WAIT0(); }
        __syncthreads();

        const uint32_t st = sm + (c & 1) * STAGE;
#pragma unroll
        for (int ks = 0; ks < 2; ks++) {
            uint32_t bb[4][2];
            const uint32_t brw = ks * 16 + (lane & 15);
            const uint32_t bco = (wn + ((lane >> 4) * 8)) * 2;
#pragma unroll
            for (int p = 0; p < 2; p++) {
                uint32_t addr = st + brw * B_PITCH + bco + p * 32;
                ldsm_x4_t(addr + OFF_B, bb[2 * p][0], bb[2 * p][1], bb[2 * p + 1][0], bb[2 * p + 1][1]);
            }
            const uint32_t arow = wm + (lane & 15);
            const uint32_t acol = ((lane >> 4) * 8 + ks * 16) * 2;
#pragma unroll
            for (int mf = 0; mf < 4; mf++) {
                uint32_t aa[4];
                uint32_t addr = st + (arow + mf * 16) * A_PITCH + acol;
                ldsm_x4(addr + OFF_A, aa[0], aa[1], aa[2], aa[3]);
#pragma unroll
                for (int nb = 0; nb < 4; nb++) {
                    float* d = acc[mf][nb];
                    mma_fp16(d[0], d[1], d[2], d[3],
                             aa[0], aa[1], aa[2], aa[3], bb[nb][0], bb[nb][1]);
                }
            }
        }
        __syncthreads();
    }

    // ---- epilogue ----
    const float* bp = bias + (size_t)e * N + n0;
#pragma unroll
    for (int mf = 0; mf < 4; mf++)
#pragma unroll
        for (int nb = 0; nb < 4; nb++) {
            const int c  = wn + nb * 8 + (lane & 3) * 2;
            const float b0 = bp[c], b1 = bp[c + 1];
#pragma unroll
            for (int half = 0; half < 2; half++) {
                const int r = wm + mf * 16 + (lane >> 2) + half * 8;
                if (r < rows) {
                    float f0 = acc[mf][nb][half * 2]     + b0;
                    float f1 = acc[mf][nb][half * 2 + 1] + b1;
                    if (RELU) { f0 = fmaxf(f0, 0.f); f1 = fmaxf(f1, 0.f); }
                    const size_t grow = (size_t)(off + m0 + r);
                    const size_t o = grow * N + n0 + c;
                    if (OUT_HALF) {
                        __half2 hp = {__float2half_rn(f0), __float2half_rn(f1)};
                        *reinterpret_cast<__half2*>(Ch + o) = hp;
                    } else {
                        float2 v = {f0, f1};
                        *reinterpret_cast<float2*>(Cf + o) = v;
                    }
                }
            }
        }
}

// out[t] = w0*y[row0] + w1*y[row1]
__global__ void combine_kernel(float* __restrict__ out) {
    int t = blockIdx.x;
    float w0 = g_gw[2 * t], w1 = g_gw[2 * t + 1];
    const float4* y0 = reinterpret_cast<const float4*>(g_y + (size_t)g_rowof[2 * t]     * D_MODEL);
    const float4* y1 = reinterpret_cast<const float4*>(g_y + (size_t)g_rowof[2 * t + 1] * D_MODEL);
    float4* o = reinterpret_cast<float4*>(out + (size_t)t * D_MODEL);
    int i = threadIdx.x;
    float4 a = y0[i], b = y1[i];
    float4 r;
    r.x = w0 * a.x + w1 * b.x;
    r.y = w0 * a.y + w1 * b.y;
    r.z = w0 * a.z + w1 * b.z;
    r.w = w0 * a.w + w1 * b.w;
    o[i] = r;
}

// ---------------- launch ----------------
extern "C" void kernel_launch(void* const* d_in, const int* in_sizes, int n_in,
                              void* d_out, int out_size) {
    const float* x  = (const float*)d_in[0];
    const float* Wg = (const float*)d_in[1];
    const float* W1 = (const float*)d_in[2];
    const float* b1 = (const float*)d_in[3];
    const float* W2 = (const float*)d_in[4];
    const float* b2 = (const float*)d_in[5];
    float* out = (float*)d_out;

    const int T = in_sizes[0] / D_MODEL;   // 4096

    __half *x16, *w1, *w2, *h16;
    float* ybuf;
    cudaGetSymbolAddress((void**)&x16, g_x16);
    cudaGetSymbolAddress((void**)&w1,  g_w1);
    cudaGetSymbolAddress((void**)&w2,  g_w2);
    cudaGetSymbolAddress((void**)&h16, g_h16);
    cudaGetSymbolAddress((void**)&ybuf, g_y);

    cudaFuncSetAttribute(mma_gemm<true, true, true>,
                         cudaFuncAttributeMaxDynamicSharedMemorySize, SMEM_SZ);
    cudaFuncSetAttribute(mma_gemm<false, false, false>,
                         cudaFuncAttributeMaxDynamicSharedMemorySize, SMEM_SZ);

    zero_kernel<<<1, 32>>>();
    gate_kernel<<<(T * 32 + 255) / 256, 256>>>(x, Wg, T);
    route_kernel<<<1, 256>>>(T);

    size_t nx = (size_t)T * D_MODEL;
    size_t nw = (size_t)N_EXP * D_MODEL * D_FF;
    conv_kernel<<<(unsigned)((nx / 8 + 255) / 256), 256>>>(x,  x16, nx);
    conv_kernel<<<(unsigned)((nw / 8 + 255) / 256), 256>>>(W1, w1,  nw);
    conv_kernel<<<(unsigned)((nw / 8 + 255) / 256), 256>>>(W2, w2,  nw);

    // GEMM1: h = relu(x @ W1 + b1), fp16 out
    mma_gemm<true, true, true><<<dim3(D_FF / 128, MAX_T / 128, N_EXP), 256, SMEM_SZ>>>(
        x16, w1, b1, nullptr, h16, D_MODEL, D_FF);
    // GEMM2: y = h @ W2 + b2, fp32 out
    mma_gemm<false, false, false><<<dim3(D_MODEL / 128, MAX_T / 128, N_EXP), 256, SMEM_SZ>>>(
        h16, w2, b2, ybuf, nullptr, D_FF, D_MODEL);

    combine_kernel<<<T, 256>>>(out);
}